// round 5
// baseline (speedup 1.0000x reference)
#include <cuda_runtime.h>
#include <cstdint>

#define N_NODES 40000
#define N_EDGES 640000
#define IN_DIM  128
#define HID     256

// ---------------- device scratch (static, no allocations) ----------------
__device__ int   g_is64;
__device__ int   g_srcs[N_EDGES];
__device__ int   g_dsts[N_EDGES];
__device__ int   g_count[N_NODES];
__device__ int   g_rowstart[N_NODES + 1];
__device__ int   g_cursor[N_NODES];
__device__ int   g_src[N_EDGES];
__device__ __align__(16) float g_agg[(size_t)N_NODES * HID];
__device__ __align__(16) float g_h  [(size_t)N_NODES * HID];
__device__ __align__(16) float g_h2 [(size_t)N_NODES * HID];

// ---------------- edge-index dtype detection ----------------
__global__ void k_detect(const int* __restrict__ ei_w) {
    __shared__ int acc;
    if (threadIdx.x == 0) acc = 0;
    __syncthreads();
    int v = 0;
    for (int i = threadIdx.x; i < 2048; i += 256) v |= ei_w[2 * i + 1];
    atomicOr(&acc, v);
    __syncthreads();
    if (threadIdx.x == 0) g_is64 = (acc == 0) ? 1 : 0;
}

__device__ __forceinline__ int clampN(int v) {
    return v < 0 ? 0 : (v >= N_NODES ? N_NODES - 1 : v);
}

__global__ void k_zero_counts() {
    int i = blockIdx.x * blockDim.x + threadIdx.x;
    if (i < N_NODES) g_count[i] = 0;
}

// fused: normalize edge list (dtype-agnostic) + histogram dst degrees
__global__ void k_extract_count(const int* __restrict__ ei_w) {
    int e = blockIdx.x * blockDim.x + threadIdx.x;
    if (e >= N_EDGES) return;
    int s, d;
    if (g_is64) {
        s = ei_w[2 * (size_t)e];
        d = ei_w[2 * ((size_t)N_EDGES + e)];
    } else {
        s = ei_w[e];
        d = ei_w[N_EDGES + e];
    }
    s = clampN(s); d = clampN(d);
    g_srcs[e] = s;
    g_dsts[e] = d;
    atomicAdd(&g_count[d], 1);
}

__global__ void k_scan_counts() {
    __shared__ int part[1024];
    const int t   = threadIdx.x;
    const int PER = (N_NODES + 1023) / 1024;   // 40
    const int base = t * PER;
    int s = 0;
    for (int j = 0; j < PER; j++) {
        int idx = base + j;
        if (idx < N_NODES) s += g_count[idx];
    }
    part[t] = s;
    __syncthreads();
    for (int off = 1; off < 1024; off <<= 1) {
        int v = (t >= off) ? part[t - off] : 0;
        __syncthreads();
        part[t] += v;
        __syncthreads();
    }
    int run = (t == 0) ? 0 : part[t - 1];
    for (int j = 0; j < PER; j++) {
        int idx = base + j;
        if (idx < N_NODES) {
            g_rowstart[idx] = run;
            g_cursor[idx]   = run;
            run += g_count[idx];
        }
    }
    if (t == 1023) g_rowstart[N_NODES] = part[1023];
}

__global__ void k_fill_src() {
    int e = blockIdx.x * blockDim.x + threadIdx.x;
    if (e < N_EDGES) {
        int pos = atomicAdd(&g_cursor[g_dsts[e]], 1);
        g_src[pos] = g_srcs[e];
    }
}

// ---------------- mean aggregation over in-edges ----------------
template <int D>
__global__ void k_aggregate(const float* __restrict__ x, float* __restrict__ out) {
    constexpr int TPN = D / 4;
    constexpr int NPB = 256 / TPN;
    int node = blockIdx.x * NPB + threadIdx.x / TPN;
    int lane = threadIdx.x % TPN;
    if (node >= N_NODES) return;

    const int beg = g_rowstart[node];
    const int end = g_rowstart[node + 1];
    const float4* xv = (const float4*)x;

    float ax = 0.f, ay = 0.f, az = 0.f, aw = 0.f;
    int j = beg;
    for (; j + 4 <= end; j += 4) {
        int s0 = g_src[j + 0], s1 = g_src[j + 1], s2 = g_src[j + 2], s3 = g_src[j + 3];
        float4 v0 = xv[(size_t)s0 * TPN + lane];
        float4 v1 = xv[(size_t)s1 * TPN + lane];
        float4 v2 = xv[(size_t)s2 * TPN + lane];
        float4 v3 = xv[(size_t)s3 * TPN + lane];
        ax += v0.x + v1.x + v2.x + v3.x;
        ay += v0.y + v1.y + v2.y + v3.y;
        az += v0.z + v1.z + v2.z + v3.z;
        aw += v0.w + v1.w + v2.w + v3.w;
    }
    for (; j < end; j++) {
        float4 v = xv[(size_t)g_src[j] * TPN + lane];
        ax += v.x; ay += v.y; az += v.z; aw += v.w;
    }
    float inv = (end > beg) ? 1.f / (float)(end - beg) : 0.f;
    float4 r = make_float4(ax * inv, ay * inv, az * inv, aw * inv);
    ((float4*)out)[(size_t)node * TPN + lane] = r;
}

// ---------------- tf32 tensor-core fused dual-source GEMM ----------------
// C[M, 256] = A0 @ W0^T + A1 @ W1^T + b   (optional ReLU)
// BM=BN=128, BK=32, 256 threads (8 warps: 4 M x 2 N), warp tile 32x64.
// Register-level software pipeline: tile t+1 LDGs issue before tile t barriers.
__device__ __forceinline__ uint32_t f2tf32(float v) {
    uint32_t o;
    asm("cvt.rna.tf32.f32 %0, %1;" : "=r"(o) : "f"(v));
    return o;
}

__device__ __forceinline__ void mma_tf32(float* c,
                                         uint32_t a0, uint32_t a1, uint32_t a2, uint32_t a3,
                                         uint32_t b0, uint32_t b1) {
    asm volatile(
        "mma.sync.aligned.m16n8k8.row.col.f32.tf32.tf32.f32 "
        "{%0,%1,%2,%3}, {%4,%5,%6,%7}, {%8,%9}, {%0,%1,%2,%3};"
        : "+f"(c[0]), "+f"(c[1]), "+f"(c[2]), "+f"(c[3])
        : "r"(a0), "r"(a1), "r"(a2), "r"(a3), "r"(b0), "r"(b1));
}

__global__ __launch_bounds__(256, 2)
void k_sage_gemm_tc(const float* __restrict__ A0, const float* __restrict__ W0,
                    const float* __restrict__ A1, const float* __restrict__ W1,
                    int K, const float* __restrict__ bias,
                    float* __restrict__ C, int do_relu) {
    constexpr int BM = 128, BN = 128, BK = 32;
    constexpr int LDS = BK + 4;                 // 36: fragment reads conflict-free
    __shared__ uint32_t As[BM][LDS];
    __shared__ uint32_t Bs[BN][LDS];

    const int t    = threadIdx.x;
    const int warp = t >> 5, lane = t & 31;
    const int g    = lane >> 2, tg = lane & 3;
    const int wm   = warp & 3;
    const int wn   = warp >> 2;
    const int row0 = blockIdx.x * BM;
    const int col0 = blockIdx.y * BN;

    const int lr = t >> 3;                      // 0..31 load row
    const int kq = t & 7;                       // 0..7  load k-quad

    const int tilesPerSrc = K / BK;
    const int nTiles = 2 * tilesPerSrc;

    float acc[2][8][4] = {};
    float4 pa[4], pb[4];

    // prologue: load tile 0
    {
        #pragma unroll
        for (int i = 0; i < 4; i++) {
            int row = lr + 32 * i;
            pa[i] = make_float4(0.f, 0.f, 0.f, 0.f);
            if (row0 + row < N_NODES)
                pa[i] = *(const float4*)&A0[(size_t)(row0 + row) * K + kq * 4];
            pb[i] = *(const float4*)&W0[(size_t)(col0 + row) * K + kq * 4];
        }
    }

    for (int tile = 0; tile < nTiles; ++tile) {
        float4 na[4], nb[4];
        if (tile + 1 < nTiles) {
            int nt_ = tile + 1;
            const float* A = (nt_ < tilesPerSrc) ? A0 : A1;
            const float* W = (nt_ < tilesPerSrc) ? W0 : W1;
            int kt = (nt_ < tilesPerSrc ? nt_ : nt_ - tilesPerSrc) * BK;
            #pragma unroll
            for (int i = 0; i < 4; i++) {
                int row = lr + 32 * i;
                na[i] = make_float4(0.f, 0.f, 0.f, 0.f);
                if (row0 + row < N_NODES)
                    na[i] = *(const float4*)&A[(size_t)(row0 + row) * K + kt + kq * 4];
                nb[i] = *(const float4*)&W[(size_t)(col0 + row) * K + kt + kq * 4];
            }
        }

        __syncthreads();   // previous tile's MMA readers done
        #pragma unroll
        for (int i = 0; i < 4; i++) {
            int row = lr + 32 * i;
            As[row][kq * 4 + 0] = f2tf32(pa[i].x);
            As[row][kq * 4 + 1] = f2tf32(pa[i].y);
            As[row][kq * 4 + 2] = f2tf32(pa[i].z);
            As[row][kq * 4 + 3] = f2tf32(pa[i].w);
            Bs[row][kq * 4 + 0] = f2tf32(pb[i].x);
            Bs[row][kq * 4 + 1] = f2tf32(pb[i].y);
            Bs[row][kq * 4 + 2] = f2tf32(pb[i].z);
            Bs[row][kq * 4 + 3] = f2tf32(pb[i].w);
        }
        __syncthreads();

        #pragma unroll
        for (int kk = 0; kk < BK; kk += 8) {
            uint32_t bf[8][2];
            #pragma unroll
            for (int nt = 0; nt < 8; nt++) {
                int n = wn * 64 + nt * 8 + g;
                bf[nt][0] = Bs[n][kk + tg];
                bf[nt][1] = Bs[n][kk + tg + 4];
            }
            #pragma unroll
            for (int mt = 0; mt < 2; mt++) {
                int r = wm * 32 + mt * 16 + g;
                uint32_t a0 = As[r    ][kk + tg];
                uint32_t a1 = As[r + 8][kk + tg];
                uint32_t a2 = As[r    ][kk + tg + 4];
                uint32_t a3 = As[r + 8][kk + tg + 4];
                #pragma unroll
                for (int nt = 0; nt < 8; nt++)
                    mma_tf32(acc[mt][nt], a0, a1, a2, a3, bf[nt][0], bf[nt][1]);
            }
        }

        #pragma unroll
        for (int i = 0; i < 4; i++) { pa[i] = na[i]; pb[i] = nb[i]; }
    }

    // epilogue: bias (+ReLU), predicated rows
    #pragma unroll
    for (int mt = 0; mt < 2; mt++) {
        int r = row0 + wm * 32 + mt * 16 + g;
        #pragma unroll
        for (int nt = 0; nt < 8; nt++) {
            int col = col0 + wn * 64 + nt * 8 + tg * 2;
            float2 bv = *(const float2*)&bias[col];
            float v0 = acc[mt][nt][0] + bv.x;
            float v1 = acc[mt][nt][1] + bv.y;
            float v2 = acc[mt][nt][2] + bv.x;
            float v3 = acc[mt][nt][3] + bv.y;
            if (do_relu) {
                v0 = fmaxf(v0, 0.f); v1 = fmaxf(v1, 0.f);
                v2 = fmaxf(v2, 0.f); v3 = fmaxf(v3, 0.f);
            }
            if (r < N_NODES)     *(float2*)&C[(size_t)r * HID + col]       = make_float2(v0, v1);
            if (r + 8 < N_NODES) *(float2*)&C[(size_t)(r + 8) * HID + col] = make_float2(v2, v3);
        }
    }
}

// ---------------- launch ----------------
extern "C" void kernel_launch(void* const* d_in, const int* in_sizes, int n_in,
                              void* d_out, int out_size) {
    const float* x   = (const float*)d_in[0];
    const int*   eiw = (const int*)d_in[1];
    const float* Wl1 = (const float*)d_in[2];
    const float* Wr1 = (const float*)d_in[3];
    const float* b1  = (const float*)d_in[4];
    const float* Wl2 = (const float*)d_in[5];
    const float* Wr2 = (const float*)d_in[6];
    const float* b2  = (const float*)d_in[7];
    const float* Wl3 = (const float*)d_in[8];
    const float* Wr3 = (const float*)d_in[9];
    const float* b3  = (const float*)d_in[10];
    float*       out = (float*)d_out;

    float *agg, *h, *h2;
    cudaGetSymbolAddress((void**)&agg, g_agg);
    cudaGetSymbolAddress((void**)&h,   g_h);
    cudaGetSymbolAddress((void**)&h2,  g_h2);

    // CSR build (detect dtype -> normalize+count -> scan -> fill)
    k_zero_counts<<<(N_NODES + 255) / 256, 256>>>();
    k_detect<<<1, 256>>>(eiw);
    k_extract_count<<<(N_EDGES + 255) / 256, 256>>>(eiw);
    k_scan_counts<<<1, 1024>>>();
    k_fill_src<<<(N_EDGES + 255) / 256, 256>>>();

    dim3 ggrid((N_NODES + 127) / 128, HID / 128);   // 313 x 2

    // Layer 1: 128 -> 256, relu
    k_aggregate<IN_DIM><<<(N_NODES + 7) / 8, 256>>>(x, agg);
    k_sage_gemm_tc<<<ggrid, 256>>>(agg, Wl1, x, Wr1, IN_DIM, b1, h, 1);

    // Layer 2: 256 -> 256, relu
    k_aggregate<HID><<<(N_NODES + 3) / 4, 256>>>(h, agg);
    k_sage_gemm_tc<<<ggrid, 256>>>(agg, Wl2, h, Wr2, HID, b2, h2, 1);

    // Layer 3: 256 -> 256, no relu, write d_out
    k_aggregate<HID><<<(N_NODES + 3) / 4, 256>>>(h2, agg);
    k_sage_gemm_tc<<<ggrid, 256>>>(agg, Wl3, h2, Wr3, HID, b3, out, 0);
}

// round 6
// speedup vs baseline: 1.3004x; 1.3004x over previous
#include <cuda_runtime.h>
#include <cstdint>

#define N_NODES 40000
#define N_EDGES 640000
#define IN_DIM  128
#define HID     256

#define SCAN_BLOCKS 40
#define SCAN_CHUNK  1000   // 40 * 1000 = 40000 exactly

// ---------------- device scratch (static, no allocations) ----------------
__device__ int   g_is64;
__device__ int   g_srcs[N_EDGES];
__device__ int   g_dsts[N_EDGES];
__device__ int   g_count[N_NODES];
__device__ int   g_rowstart[N_NODES + 1];
__device__ int   g_cursor[N_NODES];
__device__ int   g_src[N_EDGES];
__device__ int   g_blocksum[SCAN_BLOCKS];
__device__ int   g_blockoff[SCAN_BLOCKS];
__device__ __align__(16) float g_agg[(size_t)N_NODES * HID];
__device__ __align__(16) float g_h  [(size_t)N_NODES * HID];
__device__ __align__(16) float g_h2 [(size_t)N_NODES * HID];

// ---------------- edge-index dtype detection ----------------
__global__ void k_detect(const int* __restrict__ ei_w) {
    __shared__ int acc;
    if (threadIdx.x == 0) acc = 0;
    __syncthreads();
    int v = 0;
    for (int i = threadIdx.x; i < 2048; i += 256) v |= ei_w[2 * i + 1];
    atomicOr(&acc, v);
    __syncthreads();
    if (threadIdx.x == 0) g_is64 = (acc == 0) ? 1 : 0;
}

__device__ __forceinline__ int clampN(int v) {
    return v < 0 ? 0 : (v >= N_NODES ? N_NODES - 1 : v);
}

__global__ void k_zero_counts() {
    int i = blockIdx.x * blockDim.x + threadIdx.x;
    if (i < N_NODES) g_count[i] = 0;
}

// fused: normalize edge list (dtype-agnostic) + histogram dst degrees
__global__ void k_extract_count(const int* __restrict__ ei_w) {
    int e = blockIdx.x * blockDim.x + threadIdx.x;
    if (e >= N_EDGES) return;
    int s, d;
    if (g_is64) {
        s = ei_w[2 * (size_t)e];
        d = ei_w[2 * ((size_t)N_EDGES + e)];
    } else {
        s = ei_w[e];
        d = ei_w[N_EDGES + e];
    }
    s = clampN(s); d = clampN(d);
    g_srcs[e] = s;
    g_dsts[e] = d;
    atomicAdd(&g_count[d], 1);
}

// ---------------- 3-phase decoupled scan over 40000 counts ----------------
// Phase 1: each of 40 blocks scans its coalesced 1000-elem chunk in smem,
// writes LOCAL exclusive prefix to g_rowstart and its total to g_blocksum.
__global__ void k_scan_phase1() {
    __shared__ int sm[1024];
    const int b = blockIdx.x, t = threadIdx.x;
    const int idx = b * SCAN_CHUNK + t;
    int v = (t < SCAN_CHUNK) ? g_count[idx] : 0;
    sm[t] = v;
    __syncthreads();
    for (int off = 1; off < 1024; off <<= 1) {
        int u = (t >= off) ? sm[t - off] : 0;
        __syncthreads();
        sm[t] += u;
        __syncthreads();
    }
    if (t < SCAN_CHUNK) g_rowstart[idx] = sm[t] - v;   // local exclusive
    if (t == 1023) g_blocksum[b] = sm[1023];
}

// Phase 2: exclusive scan of the 40 block sums (one warp).
__global__ void k_scan_phase2() {
    if (threadIdx.x == 0) {
        int run = 0;
        for (int i = 0; i < SCAN_BLOCKS; i++) {
            g_blockoff[i] = run;
            run += g_blocksum[i];
        }
        g_rowstart[N_NODES] = run;   // total edge count
    }
}

// Phase 3: add block offsets; write final rowstart + cursor (coalesced).
__global__ void k_scan_phase3() {
    const int b = blockIdx.x, t = threadIdx.x;
    if (t < SCAN_CHUNK) {
        int idx = b * SCAN_CHUNK + t;
        int rs = g_rowstart[idx] + g_blockoff[b];
        g_rowstart[idx] = rs;
        g_cursor[idx]   = rs;
    }
}

__global__ void k_fill_src() {
    int e = blockIdx.x * blockDim.x + threadIdx.x;
    if (e < N_EDGES) {
        int pos = atomicAdd(&g_cursor[g_dsts[e]], 1);
        g_src[pos] = g_srcs[e];
    }
}

// ---------------- mean aggregation over in-edges ----------------
template <int D>
__global__ void k_aggregate(const float* __restrict__ x, float* __restrict__ out) {
    constexpr int TPN = D / 4;
    constexpr int NPB = 256 / TPN;
    int node = blockIdx.x * NPB + threadIdx.x / TPN;
    int lane = threadIdx.x % TPN;
    if (node >= N_NODES) return;

    const int beg = g_rowstart[node];
    const int end = g_rowstart[node + 1];
    const float4* xv = (const float4*)x;

    float ax = 0.f, ay = 0.f, az = 0.f, aw = 0.f;
    int j = beg;
    for (; j + 4 <= end; j += 4) {
        int s0 = g_src[j + 0], s1 = g_src[j + 1], s2 = g_src[j + 2], s3 = g_src[j + 3];
        float4 v0 = xv[(size_t)s0 * TPN + lane];
        float4 v1 = xv[(size_t)s1 * TPN + lane];
        float4 v2 = xv[(size_t)s2 * TPN + lane];
        float4 v3 = xv[(size_t)s3 * TPN + lane];
        ax += v0.x + v1.x + v2.x + v3.x;
        ay += v0.y + v1.y + v2.y + v3.y;
        az += v0.z + v1.z + v2.z + v3.z;
        aw += v0.w + v1.w + v2.w + v3.w;
    }
    for (; j < end; j++) {
        float4 v = xv[(size_t)g_src[j] * TPN + lane];
        ax += v.x; ay += v.y; az += v.z; aw += v.w;
    }
    float inv = (end > beg) ? 1.f / (float)(end - beg) : 0.f;
    float4 r = make_float4(ax * inv, ay * inv, az * inv, aw * inv);
    ((float4*)out)[(size_t)node * TPN + lane] = r;
}

// ---------------- tf32 tensor-core fused dual-source GEMM (Round-4 form) ----
__device__ __forceinline__ uint32_t f2tf32(float v) {
    uint32_t o;
    asm("cvt.rna.tf32.f32 %0, %1;" : "=r"(o) : "f"(v));
    return o;
}

__device__ __forceinline__ void mma_tf32(float* c,
                                         uint32_t a0, uint32_t a1, uint32_t a2, uint32_t a3,
                                         uint32_t b0, uint32_t b1) {
    asm volatile(
        "mma.sync.aligned.m16n8k8.row.col.f32.tf32.tf32.f32 "
        "{%0,%1,%2,%3}, {%4,%5,%6,%7}, {%8,%9}, {%0,%1,%2,%3};"
        : "+f"(c[0]), "+f"(c[1]), "+f"(c[2]), "+f"(c[3])
        : "r"(a0), "r"(a1), "r"(a2), "r"(a3), "r"(b0), "r"(b1));
}

__global__ __launch_bounds__(256, 2)
void k_sage_gemm_tc(const float* __restrict__ A0, const float* __restrict__ W0,
                    const float* __restrict__ A1, const float* __restrict__ W1,
                    int K, const float* __restrict__ bias,
                    float* __restrict__ C, int do_relu) {
    constexpr int BM = 128, BN = 128, BK = 32;
    constexpr int LDS = BK + 4;
    __shared__ uint32_t As[BM][LDS];
    __shared__ uint32_t Bs[BN][LDS];

    const int t    = threadIdx.x;
    const int warp = t >> 5, lane = t & 31;
    const int g    = lane >> 2, tg = lane & 3;
    const int wm   = warp & 3;
    const int wn   = warp >> 2;
    const int row0 = blockIdx.x * BM;
    const int col0 = blockIdx.y * BN;

    const int lr = t >> 3;
    const int kq = t & 7;

    float acc[2][8][4] = {};

    #pragma unroll 1
    for (int srcSel = 0; srcSel < 2; ++srcSel) {
        const float* A = srcSel ? A1 : A0;
        const float* W = srcSel ? W1 : W0;
        for (int kt = 0; kt < K; kt += BK) {
            __syncthreads();
            #pragma unroll
            for (int i = 0; i < 4; i++) {
                int row = lr + 32 * i;
                float4 av = make_float4(0.f, 0.f, 0.f, 0.f);
                if (row0 + row < N_NODES)
                    av = *(const float4*)&A[(size_t)(row0 + row) * K + kt + kq * 4];
                As[row][kq * 4 + 0] = f2tf32(av.x);
                As[row][kq * 4 + 1] = f2tf32(av.y);
                As[row][kq * 4 + 2] = f2tf32(av.z);
                As[row][kq * 4 + 3] = f2tf32(av.w);
                float4 wv = *(const float4*)&W[(size_t)(col0 + row) * K + kt + kq * 4];
                Bs[row][kq * 4 + 0] = f2tf32(wv.x);
                Bs[row][kq * 4 + 1] = f2tf32(wv.y);
                Bs[row][kq * 4 + 2] = f2tf32(wv.z);
                Bs[row][kq * 4 + 3] = f2tf32(wv.w);
            }
            __syncthreads();

            #pragma unroll
            for (int kk = 0; kk < BK; kk += 8) {
                uint32_t bf[8][2];
                #pragma unroll
                for (int nt = 0; nt < 8; nt++) {
                    int n = wn * 64 + nt * 8 + g;
                    bf[nt][0] = Bs[n][kk + tg];
                    bf[nt][1] = Bs[n][kk + tg + 4];
                }
                #pragma unroll
                for (int mt = 0; mt < 2; mt++) {
                    int r = wm * 32 + mt * 16 + g;
                    uint32_t a0 = As[r    ][kk + tg];
                    uint32_t a1 = As[r + 8][kk + tg];
                    uint32_t a2 = As[r    ][kk + tg + 4];
                    uint32_t a3 = As[r + 8][kk + tg + 4];
                    #pragma unroll
                    for (int nt = 0; nt < 8; nt++)
                        mma_tf32(acc[mt][nt], a0, a1, a2, a3, bf[nt][0], bf[nt][1]);
                }
            }
        }
    }

    #pragma unroll
    for (int mt = 0; mt < 2; mt++) {
        int r = row0 + wm * 32 + mt * 16 + g;
        #pragma unroll
        for (int nt = 0; nt < 8; nt++) {
            int col = col0 + wn * 64 + nt * 8 + tg * 2;
            float2 bv = *(const float2*)&bias[col];
            float v0 = acc[mt][nt][0] + bv.x;
            float v1 = acc[mt][nt][1] + bv.y;
            float v2 = acc[mt][nt][2] + bv.x;
            float v3 = acc[mt][nt][3] + bv.y;
            if (do_relu) {
                v0 = fmaxf(v0, 0.f); v1 = fmaxf(v1, 0.f);
                v2 = fmaxf(v2, 0.f); v3 = fmaxf(v3, 0.f);
            }
            if (r < N_NODES)     *(float2*)&C[(size_t)r * HID + col]       = make_float2(v0, v1);
            if (r + 8 < N_NODES) *(float2*)&C[(size_t)(r + 8) * HID + col] = make_float2(v2, v3);
        }
    }
}

// ---------------- launch ----------------
extern "C" void kernel_launch(void* const* d_in, const int* in_sizes, int n_in,
                              void* d_out, int out_size) {
    const float* x   = (const float*)d_in[0];
    const int*   eiw = (const int*)d_in[1];
    const float* Wl1 = (const float*)d_in[2];
    const float* Wr1 = (const float*)d_in[3];
    const float* b1  = (const float*)d_in[4];
    const float* Wl2 = (const float*)d_in[5];
    const float* Wr2 = (const float*)d_in[6];
    const float* b2  = (const float*)d_in[7];
    const float* Wl3 = (const float*)d_in[8];
    const float* Wr3 = (const float*)d_in[9];
    const float* b3  = (const float*)d_in[10];
    float*       out = (float*)d_out;

    float *agg, *h, *h2;
    cudaGetSymbolAddress((void**)&agg, g_agg);
    cudaGetSymbolAddress((void**)&h,   g_h);
    cudaGetSymbolAddress((void**)&h2,  g_h2);

    // CSR build
    k_zero_counts<<<(N_NODES + 255) / 256, 256>>>();
    k_detect<<<1, 256>>>(eiw);
    k_extract_count<<<(N_EDGES + 255) / 256, 256>>>(eiw);
    k_scan_phase1<<<SCAN_BLOCKS, 1024>>>();
    k_scan_phase2<<<1, 32>>>();
    k_scan_phase3<<<SCAN_BLOCKS, 1024>>>();
    k_fill_src<<<(N_EDGES + 255) / 256, 256>>>();

    dim3 ggrid((N_NODES + 127) / 128, HID / 128);   // 313 x 2

    // Layer 1: 128 -> 256, relu
    k_aggregate<IN_DIM><<<(N_NODES + 7) / 8, 256>>>(x, agg);
    k_sage_gemm_tc<<<ggrid, 256>>>(agg, Wl1, x, Wr1, IN_DIM, b1, h, 1);

    // Layer 2: 256 -> 256, relu
    k_aggregate<HID><<<(N_NODES + 3) / 4, 256>>>(h, agg);
    k_sage_gemm_tc<<<ggrid, 256>>>(agg, Wl2, h, Wr2, HID, b2, h2, 1);

    // Layer 3: 256 -> 256, no relu, write d_out
    k_aggregate<HID><<<(N_NODES + 3) / 4, 256>>>(h2, agg);
    k_sage_gemm_tc<<<ggrid, 256>>>(agg, Wl3, h2, Wr3, HID, b3, out, 0);
}

// round 7
// speedup vs baseline: 1.4650x; 1.1265x over previous
#include <cuda_runtime.h>
#include <cstdint>

#define N_NODES 40000
#define N_EDGES 640000
#define IN_DIM  128
#define HID     256

#define SCAN_BLOCKS 40
#define SCAN_CHUNK  1000   // 40 * 1000 = 40000 exactly

// ---------------- device scratch (static, no allocations) ----------------
__device__ int   g_is64;
__device__ int   g_srcs[N_EDGES];
__device__ int   g_dsts[N_EDGES];
__device__ int   g_count[N_NODES];
__device__ int   g_rowstart[N_NODES + 1];
__device__ int   g_cursor[N_NODES];
__device__ int   g_src[N_EDGES];
__device__ int   g_blocksum[SCAN_BLOCKS];
__device__ int   g_blockoff[SCAN_BLOCKS];
__device__ __align__(16) float g_agg[(size_t)N_NODES * HID];
__device__ __align__(16) float g_h  [(size_t)N_NODES * HID];
__device__ __align__(16) float g_h2 [(size_t)N_NODES * HID];
__device__ __align__(16) float g_xr [(size_t)N_NODES * IN_DIM];      // tf32-rounded x
__device__ __align__(16) float g_wr [2 * HID * IN_DIM + 4 * HID * HID]; // rounded weights

// weight scratch offsets (floats)
#define WO_L1 0
#define WO_R1 (HID * IN_DIM)                    // 32768
#define WO_L2 (2 * HID * IN_DIM)                // 65536
#define WO_R2 (2 * HID * IN_DIM + HID * HID)    // 131072
#define WO_L3 (2 * HID * IN_DIM + 2 * HID * HID)// 196608
#define WO_R3 (2 * HID * IN_DIM + 3 * HID * HID)// 262144
#define W_TOTAL (2 * HID * IN_DIM + 4 * HID * HID) // 327680

__device__ __forceinline__ uint32_t f2tf32(float v) {
    uint32_t o;
    asm("cvt.rna.tf32.f32 %0, %1;" : "=r"(o) : "f"(v));
    return o;
}
__device__ __forceinline__ float roundtf(float v) { return __uint_as_float(f2tf32(v)); }

// ---------------- edge-index dtype detection ----------------
__global__ void k_detect(const int* __restrict__ ei_w) {
    __shared__ int acc;
    if (threadIdx.x == 0) acc = 0;
    __syncthreads();
    int v = 0;
    for (int i = threadIdx.x; i < 2048; i += 256) v |= ei_w[2 * i + 1];
    atomicOr(&acc, v);
    __syncthreads();
    if (threadIdx.x == 0) g_is64 = (acc == 0) ? 1 : 0;
}

__device__ __forceinline__ int clampN(int v) {
    return v < 0 ? 0 : (v >= N_NODES ? N_NODES - 1 : v);
}

__global__ void k_zero_counts() {
    int i = blockIdx.x * blockDim.x + threadIdx.x;
    if (i < N_NODES) g_count[i] = 0;
}

__global__ void k_extract_count(const int* __restrict__ ei_w) {
    int e = blockIdx.x * blockDim.x + threadIdx.x;
    if (e >= N_EDGES) return;
    int s, d;
    if (g_is64) {
        s = ei_w[2 * (size_t)e];
        d = ei_w[2 * ((size_t)N_EDGES + e)];
    } else {
        s = ei_w[e];
        d = ei_w[N_EDGES + e];
    }
    s = clampN(s); d = clampN(d);
    g_srcs[e] = s;
    g_dsts[e] = d;
    atomicAdd(&g_count[d], 1);
}

// ---------------- 3-phase decoupled scan ----------------
__global__ void k_scan_phase1() {
    __shared__ int sm[1024];
    const int b = blockIdx.x, t = threadIdx.x;
    const int idx = b * SCAN_CHUNK + t;
    int v = (t < SCAN_CHUNK) ? g_count[idx] : 0;
    sm[t] = v;
    __syncthreads();
    for (int off = 1; off < 1024; off <<= 1) {
        int u = (t >= off) ? sm[t - off] : 0;
        __syncthreads();
        sm[t] += u;
        __syncthreads();
    }
    if (t < SCAN_CHUNK) g_rowstart[idx] = sm[t] - v;
    if (t == 1023) g_blocksum[b] = sm[1023];
}

__global__ void k_scan_phase2() {
    if (threadIdx.x == 0) {
        int run = 0;
        for (int i = 0; i < SCAN_BLOCKS; i++) {
            g_blockoff[i] = run;
            run += g_blocksum[i];
        }
        g_rowstart[N_NODES] = run;
    }
}

__global__ void k_scan_phase3() {
    const int b = blockIdx.x, t = threadIdx.x;
    if (t < SCAN_CHUNK) {
        int idx = b * SCAN_CHUNK + t;
        int rs = g_rowstart[idx] + g_blockoff[b];
        g_rowstart[idx] = rs;
        g_cursor[idx]   = rs;
    }
}

__global__ void k_fill_src() {
    int e = blockIdx.x * blockDim.x + threadIdx.x;
    if (e < N_EDGES) {
        int pos = atomicAdd(&g_cursor[g_dsts[e]], 1);
        g_src[pos] = g_srcs[e];
    }
}

// ---------------- one-time tf32 pre-rounding ----------------
__global__ void k_round_x(const float* __restrict__ src) {
    int i = blockIdx.x * blockDim.x + threadIdx.x;
    if (i < N_NODES * IN_DIM) g_xr[i] = roundtf(src[i]);
}

__global__ void k_round_weights(const float* __restrict__ Wl1, const float* __restrict__ Wr1,
                                const float* __restrict__ Wl2, const float* __restrict__ Wr2,
                                const float* __restrict__ Wl3, const float* __restrict__ Wr3) {
    int i = blockIdx.x * blockDim.x + threadIdx.x;
    if (i >= W_TOTAL) return;
    float v;
    if      (i < WO_R1) v = Wl1[i - WO_L1];
    else if (i < WO_L2) v = Wr1[i - WO_R1];
    else if (i < WO_R2) v = Wl2[i - WO_L2];
    else if (i < WO_L3) v = Wr2[i - WO_R2];
    else if (i < WO_R3) v = Wl3[i - WO_L3];
    else                v = Wr3[i - WO_R3];
    g_wr[i] = roundtf(v);
}

// ---------------- mean aggregation over in-edges (tf32-rounded output) -------
template <int D>
__global__ void k_aggregate(const float* __restrict__ x, float* __restrict__ out) {
    constexpr int TPN = D / 4;
    constexpr int NPB = 256 / TPN;
    int node = blockIdx.x * NPB + threadIdx.x / TPN;
    int lane = threadIdx.x % TPN;
    if (node >= N_NODES) return;

    const int beg = g_rowstart[node];
    const int end = g_rowstart[node + 1];
    const float4* xv = (const float4*)x;

    float ax = 0.f, ay = 0.f, az = 0.f, aw = 0.f;
    int j = beg;
    for (; j + 4 <= end; j += 4) {
        int s0 = g_src[j + 0], s1 = g_src[j + 1], s2 = g_src[j + 2], s3 = g_src[j + 3];
        float4 v0 = xv[(size_t)s0 * TPN + lane];
        float4 v1 = xv[(size_t)s1 * TPN + lane];
        float4 v2 = xv[(size_t)s2 * TPN + lane];
        float4 v3 = xv[(size_t)s3 * TPN + lane];
        ax += v0.x + v1.x + v2.x + v3.x;
        ay += v0.y + v1.y + v2.y + v3.y;
        az += v0.z + v1.z + v2.z + v3.z;
        aw += v0.w + v1.w + v2.w + v3.w;
    }
    for (; j < end; j++) {
        float4 v = xv[(size_t)g_src[j] * TPN + lane];
        ax += v.x; ay += v.y; az += v.z; aw += v.w;
    }
    float inv = (end > beg) ? 1.f / (float)(end - beg) : 0.f;
    float4 r = make_float4(roundtf(ax * inv), roundtf(ay * inv),
                           roundtf(az * inv), roundtf(aw * inv));
    ((float4*)out)[(size_t)node * TPN + lane] = r;
}

// ---------------- tf32 tensor-core fused dual-source GEMM --------------------
// cp.async double-buffered; all inputs pre-rounded to tf32 bit patterns.
// BM=BN=128, BK=32, 256 threads (8 warps: 4 M x 2 N), warp tile 32x64.
__device__ __forceinline__ void mma_tf32(float* c,
                                         uint32_t a0, uint32_t a1, uint32_t a2, uint32_t a3,
                                         uint32_t b0, uint32_t b1) {
    asm volatile(
        "mma.sync.aligned.m16n8k8.row.col.f32.tf32.tf32.f32 "
        "{%0,%1,%2,%3}, {%4,%5,%6,%7}, {%8,%9}, {%0,%1,%2,%3};"
        : "+f"(c[0]), "+f"(c[1]), "+f"(c[2]), "+f"(c[3])
        : "r"(a0), "r"(a1), "r"(a2), "r"(a3), "r"(b0), "r"(b1));
}

#define GEMM_LDS  36
#define GEMM_TILE (128 * GEMM_LDS)                 // 4608 u32 per stage buffer
#define GEMM_SMEM (4 * GEMM_TILE * 4)              // 2 A stages + 2 B stages, bytes

__global__ __launch_bounds__(256, 2)
void k_sage_gemm_tc(const float* __restrict__ A0, const float* __restrict__ W0,
                    const float* __restrict__ A1, const float* __restrict__ W1,
                    int K, const float* __restrict__ bias,
                    float* __restrict__ C, int relu_round) {
    extern __shared__ uint32_t smbuf[];            // [As0|As1|Bs0|Bs1]

    const int t    = threadIdx.x;
    const int warp = t >> 5, lane = t & 31;
    const int g    = lane >> 2, tg = lane & 3;
    const int wm   = warp & 3;
    const int wn   = warp >> 2;
    const int row0 = blockIdx.x * 128;
    const int col0 = blockIdx.y * 128;

    const int lr = t >> 3;                         // 0..31 load row
    const int kq = t & 7;                          // 0..7  load k-quad

    const int tilesPerSrc = K >> 5;
    const int nTiles = 2 * tilesPerSrc;

    float acc[2][8][4] = {};

    // --- cp.async tile issue ---
    auto issue = [&](int tile) {
        const int s = tile & 1;
        const float* A = (tile < tilesPerSrc) ? A0 : A1;
        const float* W = (tile < tilesPerSrc) ? W0 : W1;
        const int kt = ((tile < tilesPerSrc) ? tile : tile - tilesPerSrc) << 5;
        #pragma unroll
        for (int i = 0; i < 4; i++) {
            int row = lr + 32 * i;
            uint32_t da = (uint32_t)__cvta_generic_to_shared(
                &smbuf[s * GEMM_TILE + row * GEMM_LDS + kq * 4]);
            const float* ga = &A[(size_t)(row0 + row) * K + kt + kq * 4];
            int sz = (row0 + row < N_NODES) ? 16 : 0;
            asm volatile("cp.async.cg.shared.global [%0], [%1], 16, %2;"
                         :: "r"(da), "l"(ga), "r"(sz));
            uint32_t db = (uint32_t)__cvta_generic_to_shared(
                &smbuf[2 * GEMM_TILE + s * GEMM_TILE + row * GEMM_LDS + kq * 4]);
            const float* gw = &W[(size_t)(col0 + row) * K + kt + kq * 4];
            asm volatile("cp.async.cg.shared.global [%0], [%1], 16;"
                         :: "r"(db), "l"(gw));
        }
        asm volatile("cp.async.commit_group;");
    };

    issue(0);
    for (int tile = 0; tile < nTiles; ++tile) {
        if (tile + 1 < nTiles) {
            issue(tile + 1);
            asm volatile("cp.async.wait_group 1;");
        } else {
            asm volatile("cp.async.wait_group 0;");
        }
        __syncthreads();

        const uint32_t* Asb = &smbuf[(tile & 1) * GEMM_TILE];
        const uint32_t* Bsb = &smbuf[2 * GEMM_TILE + (tile & 1) * GEMM_TILE];

        #pragma unroll
        for (int kk = 0; kk < 32; kk += 8) {
            uint32_t bf[8][2];
            #pragma unroll
            for (int nt = 0; nt < 8; nt++) {
                int n = wn * 64 + nt * 8 + g;
                bf[nt][0] = Bsb[n * GEMM_LDS + kk + tg];
                bf[nt][1] = Bsb[n * GEMM_LDS + kk + tg + 4];
            }
            #pragma unroll
            for (int mt = 0; mt < 2; mt++) {
                int r = wm * 32 + mt * 16 + g;
                uint32_t a0 = Asb[(r    ) * GEMM_LDS + kk + tg];
                uint32_t a1 = Asb[(r + 8) * GEMM_LDS + kk + tg];
                uint32_t a2 = Asb[(r    ) * GEMM_LDS + kk + tg + 4];
                uint32_t a3 = Asb[(r + 8) * GEMM_LDS + kk + tg + 4];
                #pragma unroll
                for (int nt = 0; nt < 8; nt++)
                    mma_tf32(acc[mt][nt], a0, a1, a2, a3, bf[nt][0], bf[nt][1]);
            }
        }
        __syncthreads();   // MMA readers done before next issue overwrites this stage
    }

    // epilogue: bias (+ReLU + tf32 rounding when feeding another layer)
    #pragma unroll
    for (int mt = 0; mt < 2; mt++) {
        int r = row0 + wm * 32 + mt * 16 + g;
        #pragma unroll
        for (int nt = 0; nt < 8; nt++) {
            int col = col0 + wn * 64 + nt * 8 + tg * 2;
            float2 bv = *(const float2*)&bias[col];
            float v0 = acc[mt][nt][0] + bv.x;
            float v1 = acc[mt][nt][1] + bv.y;
            float v2 = acc[mt][nt][2] + bv.x;
            float v3 = acc[mt][nt][3] + bv.y;
            if (relu_round) {
                v0 = roundtf(fmaxf(v0, 0.f)); v1 = roundtf(fmaxf(v1, 0.f));
                v2 = roundtf(fmaxf(v2, 0.f)); v3 = roundtf(fmaxf(v3, 0.f));
            }
            if (r < N_NODES)     *(float2*)&C[(size_t)r * HID + col]       = make_float2(v0, v1);
            if (r + 8 < N_NODES) *(float2*)&C[(size_t)(r + 8) * HID + col] = make_float2(v2, v3);
        }
    }
}

// ---------------- launch ----------------
extern "C" void kernel_launch(void* const* d_in, const int* in_sizes, int n_in,
                              void* d_out, int out_size) {
    const float* x   = (const float*)d_in[0];
    const int*   eiw = (const int*)d_in[1];
    const float* Wl1 = (const float*)d_in[2];
    const float* Wr1 = (const float*)d_in[3];
    const float* b1  = (const float*)d_in[4];
    const float* Wl2 = (const float*)d_in[5];
    const float* Wr2 = (const float*)d_in[6];
    const float* b2  = (const float*)d_in[7];
    const float* Wl3 = (const float*)d_in[8];
    const float* Wr3 = (const float*)d_in[9];
    const float* b3  = (const float*)d_in[10];
    float*       out = (float*)d_out;

    float *agg, *h, *h2, *xr, *wr;
    cudaGetSymbolAddress((void**)&agg, g_agg);
    cudaGetSymbolAddress((void**)&h,   g_h);
    cudaGetSymbolAddress((void**)&h2,  g_h2);
    cudaGetSymbolAddress((void**)&xr,  g_xr);
    cudaGetSymbolAddress((void**)&wr,  g_wr);

    cudaFuncSetAttribute(k_sage_gemm_tc,
                         cudaFuncAttributeMaxDynamicSharedMemorySize, GEMM_SMEM);

    // CSR build
    k_zero_counts<<<(N_NODES + 255) / 256, 256>>>();
    k_detect<<<1, 256>>>(eiw);
    k_extract_count<<<(N_EDGES + 255) / 256, 256>>>(eiw);
    k_scan_phase1<<<SCAN_BLOCKS, 1024>>>();
    k_scan_phase2<<<1, 32>>>();
    k_scan_phase3<<<SCAN_BLOCKS, 1024>>>();
    k_fill_src<<<(N_EDGES + 255) / 256, 256>>>();

    // tf32 pre-rounding of GEMM-only inputs
    k_round_x<<<(N_NODES * IN_DIM + 255) / 256, 256>>>(x);
    k_round_weights<<<(W_TOTAL + 255) / 256, 256>>>(Wl1, Wr1, Wl2, Wr2, Wl3, Wr3);

    dim3 ggrid((N_NODES + 127) / 128, HID / 128);   // 313 x 2

    // Layer 1: 128 -> 256, relu (+round into h)
    k_aggregate<IN_DIM><<<(N_NODES + 7) / 8, 256>>>(x, agg);
    k_sage_gemm_tc<<<ggrid, 256, GEMM_SMEM>>>(agg, wr + WO_L1, xr, wr + WO_R1,
                                              IN_DIM, b1, h, 1);

    // Layer 2: 256 -> 256, relu (+round into h2)
    k_aggregate<HID><<<(N_NODES + 3) / 4, 256>>>(h, agg);
    k_sage_gemm_tc<<<ggrid, 256, GEMM_SMEM>>>(agg, wr + WO_L2, h, wr + WO_R2,
                                              HID, b2, h2, 1);

    // Layer 3: 256 -> 256, plain fp32 output
    k_aggregate<HID><<<(N_NODES + 3) / 4, 256>>>(h2, agg);
    k_sage_gemm_tc<<<ggrid, 256, GEMM_SMEM>>>(agg, wr + WO_L3, h2, wr + WO_R3,
                                              HID, b3, out, 0);
}